// round 6
// baseline (speedup 1.0000x reference)
#include <cuda_runtime.h>
#include <cuda_bf16.h>
#include <cstdint>

#define NPTS 16384
#define DIM  128
#define NQ   16384
#define NV   64

#define BQ    64
#define BN    128
#define NTILE (NPTS / BN)
#define EPS   10.0f
#define CAP   4096

// ---------------- device globals ----------------
__device__ unsigned char g_pb[NPTS * DIM];   // e4m3 points
__device__ unsigned char g_qb[NQ * DIM];     // e4m3 queries
__device__ float         g_psq[NPTS];

// ---------------- SMEM layout (bytes) ----------------
#define SM_A     0        // 64x128 e4m3, swizzled      (8192)
#define SM_B     8192     // 2 x 16384                  -> 40960
#define SM_PSQ   40960    // 2 x 512                    -> 41984
#define SM_CURB  41984    // 64 x u32                   -> 42240
#define SM_CNT   42240    //                            -> 42256
#define SM_CAND  42256    // CAP x u32 (16384)          -> 58640
#define SM_WIN   58640    // 64 x u64                   -> 59152
#define SM_TOTAL 59152

// ---------------- helpers ----------------
__device__ __forceinline__ uint32_t smem_u32(const void* p) {
    uint32_t a;
    asm("{ .reg .u64 t; cvta.to.shared.u64 t, %1; cvt.u32.u64 %0, t; }" : "=r"(a) : "l"(p));
    return a;
}
__device__ __forceinline__ unsigned toOrd(float f) {
    unsigned u = __float_as_uint(f);
    return (u & 0x80000000u) ? ~u : (u | 0x80000000u);
}
__device__ __forceinline__ float fromOrd(unsigned u) {
    unsigned v = (u & 0x80000000u) ? (u & 0x7fffffffu) : ~u;
    return __uint_as_float(v);
}

#define CP_ASYNC16(d, s) asm volatile("cp.async.cg.shared.global [%0], [%1], 16;" :: "r"(d), "l"(s) : "memory")

#define LDSM4(r0, r1, r2, r3, addr) \
    asm volatile("ldmatrix.sync.aligned.m8n8.x4.shared.b16 {%0,%1,%2,%3}, [%4];" \
                 : "=r"(r0), "=r"(r1), "=r"(r2), "=r"(r3) : "r"(addr))

#define MMA16832(c, a, b) \
    asm volatile("mma.sync.aligned.m16n8k32.row.col.f32.e4m3.e4m3.f32 " \
                 "{%0,%1,%2,%3}, {%4,%5,%6,%7}, {%8,%9}, {%0,%1,%2,%3};" \
                 : "+f"((c)[0]), "+f"((c)[1]), "+f"((c)[2]), "+f"((c)[3]) \
                 : "r"((a)[0]), "r"((a)[1]), "r"((a)[2]), "r"((a)[3]), \
                   "r"((b)[0]), "r"((b)[1]))

// pack two fp32 -> e4m3x2 (low byte = x)
__device__ __forceinline__ unsigned short fp8x2(float x, float y) {
    unsigned short w;
    asm("cvt.rn.satfinite.e4m3x2.f32 %0, %1, %2;" : "=h"(w) : "f"(y), "f"(x));
    return w;
}

// ---------------- kernel 0: fp32 -> e4m3 + fused |p|^2 ----------------
__global__ void cvt_kernel(const float* __restrict__ pts, const float* __restrict__ qs) {
    int i = blockIdx.x * blockDim.x + threadIdx.x;   // 8-elt chunk index
    const int half = NPTS * DIM / 8;
    const bool isP = (i < half);
    const float4* src = isP ? (const float4*)pts : (const float4*)qs;
    unsigned char* dst = isP ? g_pb : g_qb;
    int j = isP ? i : i - half;
    float4 a = src[(size_t)j * 2], b = src[(size_t)j * 2 + 1];
    unsigned long long w =
          (unsigned long long)fp8x2(a.x, a.y)
        | ((unsigned long long)fp8x2(a.z, a.w) << 16)
        | ((unsigned long long)fp8x2(b.x, b.y) << 32)
        | ((unsigned long long)fp8x2(b.z, b.w) << 48);
    reinterpret_cast<unsigned long long*>(dst)[j] = w;
    if (isP) {
        float s = a.x * a.x + a.y * a.y + a.z * a.z + a.w * a.w
                + b.x * b.x + b.y * b.y + b.z * b.z + b.w * b.w;
        #pragma unroll
        for (int off = 8; off; off >>= 1) s += __shfl_xor_sync(0xffffffffu, s, off);
        if ((j & 15) == 0) g_psq[j >> 4] = s;
    }
}

// ---------------- B-tile producer (16KB + psq) ----------------
__device__ __forceinline__ void issue_tile(uint32_t sb, int t, int b, int tid) {
    const char* srcB = (const char*)(g_pb + (size_t)t * BN * DIM);
    #pragma unroll
    for (int it = 0; it < 4; it++) {
        int idx = it * 256 + tid;        // 1024 chunks of 16B
        int r = idx >> 3, c = idx & 7;
        CP_ASYNC16(sb + SM_B + b * 16384 + r * 128 + ((c ^ (r & 7)) << 4),
                   srcB + (size_t)r * 128 + c * 16);
    }
    if (tid < 32)
        CP_ASYNC16(sb + SM_PSQ + b * 512 + tid * 16,
                   (const char*)(g_psq + (size_t)t * BN) + tid * 16);
}

// ---------------- main kernel: FP8 HMMA NN search ----------------
__global__ __launch_bounds__(256, 2)
void nn_main(const float* __restrict__ points,
             const float* __restrict__ points_q,
             const float* __restrict__ values,
             float* __restrict__ out) {
    extern __shared__ char smem[];
    const uint32_t sb = smem_u32(smem);
    unsigned* curB = (unsigned*)(smem + SM_CURB);
    unsigned* cntP = (unsigned*)(smem + SM_CNT);
    unsigned* cand = (unsigned*)(smem + SM_CAND);
    unsigned long long* win = (unsigned long long*)(smem + SM_WIN);
    const float* psqS = (const float*)(smem + SM_PSQ);

    const int tid = threadIdx.x, wid = tid >> 5, lane = tid & 31;
    // warp tile 32(M) x 32(N): 2 m-warps x 4 n-warps
    const int warpM = (wid >> 2) * 32, warpN = (wid & 3) * 32;
    const int qBase = blockIdx.x * BQ;

    if (tid < BQ) { curB[tid] = toOrd(3.0e38f); win[tid] = ~0ull; }
    if (tid == 0) *cntP = 0;

    // A tile (64 queries x 128 e4m3) -> swizzled SMEM
    {
        const char* src = (const char*)(g_qb + (size_t)qBase * DIM);
        #pragma unroll
        for (int it = 0; it < 2; it++) {
            int idx = it * 256 + tid;    // 512 chunks
            int r = idx >> 3, c = idx & 7;
            CP_ASYNC16(sb + SM_A + r * 128 + ((c ^ (r & 7)) << 4),
                       src + (size_t)r * 128 + c * 16);
        }
    }
    issue_tile(sb, 0, 0, tid);
    asm volatile("cp.async.commit_group;" ::: "memory");
    asm volatile("cp.async.wait_group 0;" ::: "memory");
    __syncthreads();

    // ldmatrix address precompute
    uint32_t aB[2], aX[2];
    #pragma unroll
    for (int m = 0; m < 2; m++) {
        int r = warpM + m * 16 + (lane & 15);
        aB[m] = sb + SM_A + r * 128;
        aX[m] = r & 7;
    }
    const int aHi = lane >> 4;
    uint32_t bOf[2], bX[2];
    #pragma unroll
    for (int p = 0; p < 2; p++) {
        int n = warpN + p * 16 + (lane & 7) + ((lane >> 4) << 3);
        bOf[p] = n * 128;
        bX[p] = n & 7;
    }
    const int bHi = (lane >> 3) & 1;
    const int rLane = lane >> 2;
    const int cLane = (lane & 3) * 2;

    for (int t = 0; t < NTILE; t++) {
        const int b = t & 1;
        if (t + 1 < NTILE) {
            issue_tile(sb, t + 1, b ^ 1, tid);
            asm volatile("cp.async.commit_group;" ::: "memory");
        }

        float acc[2][4][4];
        #pragma unroll
        for (int m = 0; m < 2; m++)
            #pragma unroll
            for (int n = 0; n < 4; n++)
                #pragma unroll
                for (int k = 0; k < 4; k++) acc[m][n][k] = 0.0f;

        const uint32_t bBase = sb + SM_B + b * 16384;
        #pragma unroll
        for (int ks = 0; ks < 4; ks++) {       // k = 32 e4m3 per step
            uint32_t af[2][4], bf[2][4];
            #pragma unroll
            for (int m = 0; m < 2; m++)
                LDSM4(af[m][0], af[m][1], af[m][2], af[m][3],
                      aB[m] + ((((ks << 1) + aHi) ^ aX[m]) << 4));
            #pragma unroll
            for (int p = 0; p < 2; p++)
                LDSM4(bf[p][0], bf[p][1], bf[p][2], bf[p][3],
                      bBase + bOf[p] + ((((ks << 1) + bHi) ^ bX[p]) << 4));
            #pragma unroll
            for (int m = 0; m < 2; m++)
                #pragma unroll
                for (int n = 0; n < 4; n++)
                    MMA16832(acc[m][n], af[m], &bf[n >> 1][(n & 1) * 2]);
        }

        // ---- psq for this thread's columns ----
        float ps[4][2];
        #pragma unroll
        for (int n = 0; n < 4; n++) {
            int col = warpN + n * 8 + cLane;
            ps[n][0] = psqS[b * 128 + col];
            ps[n][1] = psqS[b * 128 + col + 1];
        }

        // ---- tile-0 warm-up: establish curB before pushing ----
        if (t == 0) {
            #pragma unroll
            for (int m = 0; m < 2; m++)
                #pragma unroll
                for (int h = 0; h < 2; h++) {
                    float mv = 3.0e38f;
                    #pragma unroll
                    for (int n = 0; n < 4; n++) {
                        mv = fminf(mv, fmaf(acc[m][n][h * 2 + 0], -2.0f, ps[n][0]));
                        mv = fminf(mv, fmaf(acc[m][n][h * 2 + 1], -2.0f, ps[n][1]));
                    }
                    int r = warpM + m * 16 + rLane + h * 8;
                    atomicMin(&curB[r], toOrd(mv));
                }
            __syncthreads();
        }

        // ---- single-pass candidate push (stale curB reads are safe) ----
        #pragma unroll
        for (int m = 0; m < 2; m++)
            #pragma unroll
            for (int h = 0; h < 2; h++) {
                const int r = warpM + m * 16 + rLane + h * 8;
                const float lim = fromOrd(curB[r]) + EPS;
                #pragma unroll
                for (int n = 0; n < 4; n++)
                    #pragma unroll
                    for (int j = 0; j < 2; j++) {
                        float s = fmaf(acc[m][n][h * 2 + j], -2.0f, ps[n][j]);
                        if (s < lim) {
                            unsigned slot = atomicAdd(cntP, 1u);
                            unsigned nIdx = (unsigned)(t * BN + warpN + n * 8 + cLane + j);
                            if (slot < CAP) cand[slot] = ((unsigned)r << 14) | nIdx;
                            atomicMin(&curB[r], toOrd(s));
                        }
                    }
            }

        asm volatile("cp.async.wait_group 0;" ::: "memory");
        __syncthreads();
    }

    // ---- exact fp32 rescore ----
    unsigned total = *cntP;
    if (total > CAP) total = CAP;
    for (unsigned c = wid; c < total; c += 8) {
        unsigned pk = cand[c];
        int q = pk >> 14, n = pk & 16383;
        float4 qv = *(const float4*)(points_q + (size_t)(qBase + q) * DIM + lane * 4);
        float4 pv = *(const float4*)(points + (size_t)n * DIM + lane * 4);
        float d = qv.x * pv.x + qv.y * pv.y + qv.z * pv.z + qv.w * pv.w;
        #pragma unroll
        for (int o = 16; o; o >>= 1) d += __shfl_xor_sync(0xffffffffu, d, o);
        if (lane == 0) {
            float s = fmaf(d, -2.0f, g_psq[n]);
            unsigned long long key = ((unsigned long long)toOrd(s) << 32) | (unsigned)n;
            atomicMin(&win[q], key);
        }
    }
    __syncthreads();

    // ---- gather values ----
    for (int i = tid; i < BQ * 16; i += 256) {
        int q = i >> 4, c4 = i & 15;
        unsigned idx = (unsigned)(win[q] & 0xFFFFFFFFu);
        *(float4*)(out + (size_t)(qBase + q) * NV + c4 * 4) =
            *(const float4*)(values + (size_t)idx * NV + c4 * 4);
    }
}

// ---------------- launch ----------------
extern "C" void kernel_launch(void* const* d_in, const int* in_sizes, int n_in,
                              void* d_out, int out_size) {
    const float* points   = (const float*)d_in[0];   // [16384,128]
    const float* values   = (const float*)d_in[1];   // [16384,64]
    const float* points_q = (const float*)d_in[2];   // [16384,128]
    float* out = (float*)d_out;

    cvt_kernel<<<(2 * NPTS * DIM / 8) / 256, 256>>>(points, points_q);

    cudaFuncSetAttribute(nn_main, cudaFuncAttributeMaxDynamicSharedMemorySize, SM_TOTAL);
    nn_main<<<NQ / BQ, 256, SM_TOTAL>>>(points, points_q, values, out);
    (void)in_sizes; (void)n_in; (void)out_size;
}

// round 7
// speedup vs baseline: 1.0198x; 1.0198x over previous
#include <cuda_runtime.h>
#include <cuda_bf16.h>
#include <cstdint>

#define NPTS 16384
#define DIM  128
#define NQ   16384
#define NV   64

#define BQ    64
#define BN    128
#define NTILE (NPTS / BN)
#define EPS   10.0f
#define CAP   4096

// ---------------- device globals ----------------
__device__ unsigned char g_pb[NPTS * DIM];   // e4m3 points
__device__ unsigned char g_qb[NQ * DIM];     // e4m3 queries
__device__ float         g_psq[NPTS];

// ---------------- SMEM layout (bytes) ----------------
#define SM_A     0        // 64x128 e4m3, swizzled      (8192)
#define SM_B     8192     // 2 x 16384                  -> 40960
#define SM_PSQ   40960    // 2 x 512                    -> 41984
#define SM_CURB  41984    // 64 x u32                   -> 42240
#define SM_CNT   42240    //                            -> 42256
#define SM_CAND  42256    // CAP x u32 (16384)          -> 58640
#define SM_WIN   58640    // 64 x u64                   -> 59152
#define SM_TOTAL 59152

// ---------------- helpers ----------------
__device__ __forceinline__ uint32_t smem_u32(const void* p) {
    uint32_t a;
    asm("{ .reg .u64 t; cvta.to.shared.u64 t, %1; cvt.u32.u64 %0, t; }" : "=r"(a) : "l"(p));
    return a;
}
__device__ __forceinline__ unsigned toOrd(float f) {
    unsigned u = __float_as_uint(f);
    return (u & 0x80000000u) ? ~u : (u | 0x80000000u);
}
__device__ __forceinline__ float fromOrd(unsigned u) {
    unsigned v = (u & 0x80000000u) ? (u & 0x7fffffffu) : ~u;
    return __uint_as_float(v);
}

#define CP_ASYNC16(d, s) asm volatile("cp.async.cg.shared.global [%0], [%1], 16;" :: "r"(d), "l"(s) : "memory")

#define LDSM4(r0, r1, r2, r3, addr) \
    asm volatile("ldmatrix.sync.aligned.m8n8.x4.shared.b16 {%0,%1,%2,%3}, [%4];" \
                 : "=r"(r0), "=r"(r1), "=r"(r2), "=r"(r3) : "r"(addr))

#define MMA16832(c, a, b) \
    asm volatile("mma.sync.aligned.m16n8k32.row.col.f32.e4m3.e4m3.f32 " \
                 "{%0,%1,%2,%3}, {%4,%5,%6,%7}, {%8,%9}, {%0,%1,%2,%3};" \
                 : "+f"((c)[0]), "+f"((c)[1]), "+f"((c)[2]), "+f"((c)[3]) \
                 : "r"((a)[0]), "r"((a)[1]), "r"((a)[2]), "r"((a)[3]), \
                   "r"((b)[0]), "r"((b)[1]))

// pack two fp32 -> e4m3x2 (low byte = x)
__device__ __forceinline__ unsigned short fp8x2(float x, float y) {
    unsigned short w;
    asm("cvt.rn.satfinite.e4m3x2.f32 %0, %1, %2;" : "=h"(w) : "f"(y), "f"(x));
    return w;
}

// ---------------- kernel 0: fp32 -> e4m3 + fused |p|^2 ----------------
__global__ void cvt_kernel(const float* __restrict__ pts, const float* __restrict__ qs) {
    int i = blockIdx.x * blockDim.x + threadIdx.x;   // 8-elt chunk index
    const int half = NPTS * DIM / 8;
    const bool isP = (i < half);
    const float4* src = isP ? (const float4*)pts : (const float4*)qs;
    unsigned char* dst = isP ? g_pb : g_qb;
    int j = isP ? i : i - half;
    float4 a = src[(size_t)j * 2], b = src[(size_t)j * 2 + 1];
    unsigned long long w =
          (unsigned long long)fp8x2(a.x, a.y)
        | ((unsigned long long)fp8x2(a.z, a.w) << 16)
        | ((unsigned long long)fp8x2(b.x, b.y) << 32)
        | ((unsigned long long)fp8x2(b.z, b.w) << 48);
    reinterpret_cast<unsigned long long*>(dst)[j] = w;
    if (isP) {
        float s = a.x * a.x + a.y * a.y + a.z * a.z + a.w * a.w
                + b.x * b.x + b.y * b.y + b.z * b.z + b.w * b.w;
        #pragma unroll
        for (int off = 8; off; off >>= 1) s += __shfl_xor_sync(0xffffffffu, s, off);
        if ((j & 15) == 0) g_psq[j >> 4] = s;
    }
}

// ---------------- B-tile producer (16KB + psq) ----------------
__device__ __forceinline__ void issue_tile(uint32_t sb, int t, int b, int tid) {
    const char* srcB = (const char*)(g_pb + (size_t)t * BN * DIM);
    #pragma unroll
    for (int it = 0; it < 4; it++) {
        int idx = it * 256 + tid;        // 1024 chunks of 16B
        int r = idx >> 3, c = idx & 7;
        CP_ASYNC16(sb + SM_B + b * 16384 + r * 128 + ((c ^ (r & 7)) << 4),
                   srcB + (size_t)r * 128 + c * 16);
    }
    if (tid < 32)
        CP_ASYNC16(sb + SM_PSQ + b * 512 + tid * 16,
                   (const char*)(g_psq + (size_t)t * BN) + tid * 16);
}

// ---------------- main kernel: FP8 HMMA NN search ----------------
__global__ __launch_bounds__(256, 2)
void nn_main(const float* __restrict__ points,
             const float* __restrict__ points_q,
             const float* __restrict__ values,
             float* __restrict__ out) {
    extern __shared__ char smem[];
    const uint32_t sb = smem_u32(smem);
    unsigned* curB = (unsigned*)(smem + SM_CURB);
    unsigned* cntP = (unsigned*)(smem + SM_CNT);
    unsigned* cand = (unsigned*)(smem + SM_CAND);
    unsigned long long* win = (unsigned long long*)(smem + SM_WIN);
    const float* psqS = (const float*)(smem + SM_PSQ);

    const int tid = threadIdx.x, wid = tid >> 5, lane = tid & 31;
    // warp tile 32(M) x 32(N): 2 m-warps x 4 n-warps
    const int warpM = (wid >> 2) * 32, warpN = (wid & 3) * 32;
    const int qBase = blockIdx.x * BQ;

    if (tid < BQ) { curB[tid] = toOrd(3.0e38f); win[tid] = ~0ull; }
    if (tid == 0) *cntP = 0;

    // A tile (64 queries x 128 e4m3) -> swizzled SMEM
    {
        const char* src = (const char*)(g_qb + (size_t)qBase * DIM);
        #pragma unroll
        for (int it = 0; it < 2; it++) {
            int idx = it * 256 + tid;    // 512 chunks
            int r = idx >> 3, c = idx & 7;
            CP_ASYNC16(sb + SM_A + r * 128 + ((c ^ (r & 7)) << 4),
                       src + (size_t)r * 128 + c * 16);
        }
    }
    issue_tile(sb, 0, 0, tid);
    asm volatile("cp.async.commit_group;" ::: "memory");
    asm volatile("cp.async.wait_group 0;" ::: "memory");
    __syncthreads();

    // ldmatrix address precompute
    uint32_t aB[2], aX[2];
    #pragma unroll
    for (int m = 0; m < 2; m++) {
        int r = warpM + m * 16 + (lane & 15);
        aB[m] = sb + SM_A + r * 128;
        aX[m] = r & 7;
    }
    const int aHi = lane >> 4;
    uint32_t bOf[2], bX[2];
    #pragma unroll
    for (int p = 0; p < 2; p++) {
        int n = warpN + p * 16 + (lane & 7) + ((lane >> 4) << 3);
        bOf[p] = n * 128;
        bX[p] = n & 7;
    }
    const int bHi = (lane >> 3) & 1;
    const int rLane = lane >> 2;
    const int cLane = (lane & 3) * 2;

    for (int t = 0; t < NTILE; t++) {
        const int b = t & 1;
        if (t + 1 < NTILE) {
            issue_tile(sb, t + 1, b ^ 1, tid);
            asm volatile("cp.async.commit_group;" ::: "memory");
        }

        float acc[2][4][4];
        #pragma unroll
        for (int m = 0; m < 2; m++)
            #pragma unroll
            for (int n = 0; n < 4; n++)
                #pragma unroll
                for (int k = 0; k < 4; k++) acc[m][n][k] = 0.0f;

        const uint32_t bBase = sb + SM_B + b * 16384;
        #pragma unroll
        for (int ks = 0; ks < 4; ks++) {       // k = 32 e4m3 per step
            uint32_t af[2][4], bf[2][4];
            #pragma unroll
            for (int m = 0; m < 2; m++)
                LDSM4(af[m][0], af[m][1], af[m][2], af[m][3],
                      aB[m] + ((((ks << 1) + aHi) ^ aX[m]) << 4));
            #pragma unroll
            for (int p = 0; p < 2; p++)
                LDSM4(bf[p][0], bf[p][1], bf[p][2], bf[p][3],
                      bBase + bOf[p] + ((((ks << 1) + bHi) ^ bX[p]) << 4));
            #pragma unroll
            for (int m = 0; m < 2; m++)
                #pragma unroll
                for (int n = 0; n < 4; n++)
                    MMA16832(acc[m][n], af[m], &bf[n >> 1][(n & 1) * 2]);
        }

        // ---- epilogue pass 1: per-row tile min -> shared running best ----
        float ps[4][2];
        #pragma unroll
        for (int n = 0; n < 4; n++) {
            int col = warpN + n * 8 + cLane;
            ps[n][0] = psqS[b * 128 + col];
            ps[n][1] = psqS[b * 128 + col + 1];
        }
        float rowMin[2][2];
        #pragma unroll
        for (int m = 0; m < 2; m++)
            #pragma unroll
            for (int h = 0; h < 2; h++) {
                float mv = 3.0e38f;
                #pragma unroll
                for (int n = 0; n < 4; n++) {
                    mv = fminf(mv, fmaf(acc[m][n][h * 2 + 0], -2.0f, ps[n][0]));
                    mv = fminf(mv, fmaf(acc[m][n][h * 2 + 1], -2.0f, ps[n][1]));
                }
                rowMin[m][h] = mv;
                int r = warpM + m * 16 + rLane + h * 8;
                if (toOrd(mv) < curB[r]) atomicMin(&curB[r], toOrd(mv));
            }
        __syncthreads();

        // ---- epilogue pass 2: push margin candidates (gated, rare) ----
        #pragma unroll
        for (int m = 0; m < 2; m++)
            #pragma unroll
            for (int h = 0; h < 2; h++) {
                int r = warpM + m * 16 + rLane + h * 8;
                float lim = fromOrd(curB[r]) + EPS;
                if (rowMin[m][h] < lim) {
                    #pragma unroll
                    for (int n = 0; n < 4; n++)
                        #pragma unroll
                        for (int j = 0; j < 2; j++) {
                            float s = fmaf(acc[m][n][h * 2 + j], -2.0f, ps[n][j]);
                            if (s < lim) {
                                unsigned slot = atomicAdd(cntP, 1u);
                                unsigned nIdx = (unsigned)(t * BN + warpN + n * 8 + cLane + j);
                                if (slot < CAP) cand[slot] = ((unsigned)r << 14) | nIdx;
                            }
                        }
                }
            }

        asm volatile("cp.async.wait_group 0;" ::: "memory");
        __syncthreads();
    }

    // ---- exact fp32 rescore ----
    unsigned total = *cntP;
    if (total > CAP) total = CAP;
    for (unsigned c = wid; c < total; c += 8) {
        unsigned pk = cand[c];
        int q = pk >> 14, n = pk & 16383;
        float4 qv = *(const float4*)(points_q + (size_t)(qBase + q) * DIM + lane * 4);
        float4 pv = *(const float4*)(points + (size_t)n * DIM + lane * 4);
        float d = qv.x * pv.x + qv.y * pv.y + qv.z * pv.z + qv.w * pv.w;
        #pragma unroll
        for (int o = 16; o; o >>= 1) d += __shfl_xor_sync(0xffffffffu, d, o);
        if (lane == 0) {
            float s = fmaf(d, -2.0f, g_psq[n]);
            unsigned long long key = ((unsigned long long)toOrd(s) << 32) | (unsigned)n;
            atomicMin(&win[q], key);
        }
    }
    __syncthreads();

    // ---- gather values ----
    for (int i = tid; i < BQ * 16; i += 256) {
        int q = i >> 4, c4 = i & 15;
        unsigned idx = (unsigned)(win[q] & 0xFFFFFFFFu);
        *(float4*)(out + (size_t)(qBase + q) * NV + c4 * 4) =
            *(const float4*)(values + (size_t)idx * NV + c4 * 4);
    }
}

// ---------------- launch ----------------
extern "C" void kernel_launch(void* const* d_in, const int* in_sizes, int n_in,
                              void* d_out, int out_size) {
    const float* points   = (const float*)d_in[0];   // [16384,128]
    const float* values   = (const float*)d_in[1];   // [16384,64]
    const float* points_q = (const float*)d_in[2];   // [16384,128]
    float* out = (float*)d_out;

    cvt_kernel<<<(2 * NPTS * DIM / 8) / 256, 256>>>(points, points_q);

    cudaFuncSetAttribute(nn_main, cudaFuncAttributeMaxDynamicSharedMemorySize, SM_TOTAL);
    nn_main<<<NQ / BQ, 256, SM_TOTAL>>>(points, points_q, values, out);
    (void)in_sizes; (void)n_in; (void)out_size;
}

// round 9
// speedup vs baseline: 1.6141x; 1.5827x over previous
#include <cuda_runtime.h>
#include <cuda_bf16.h>
#include <cstdint>

#define NPTS 16384
#define DIM  128
#define NQ   16384
#define NV   64

#define BQ    64
#define BN    128
#define NTILE (NPTS / BN)
#define EPS   0.75f
#define CAP   4096

// ---------------- device globals ----------------
__device__ __nv_bfloat16 g_pb[NPTS * DIM];
__device__ __nv_bfloat16 g_qb[NQ * DIM];
__device__ float         g_psq[NPTS];

// ---------------- SMEM layout (bytes) ----------------
#define SM_A     0        // 64x128 bf16, swizzled     (16384)
#define SM_B     16384    // 2 x 32768                 -> 81920
#define SM_PSQ   81920    // 2 x 512                   -> 82944
#define SM_CURB  82944    // 64 x u32                  -> 83200
#define SM_CNT   83200    //                           -> 83216
#define SM_CAND  83216    // CAP x u32 (16384)         -> 99600
#define SM_WIN   99600    // 64 x u64                  -> 100112
#define SM_TOTAL 100112

// ---------------- helpers ----------------
__device__ __forceinline__ uint32_t smem_u32(const void* p) {
    uint32_t a;
    asm("{ .reg .u64 t; cvta.to.shared.u64 t, %1; cvt.u32.u64 %0, t; }" : "=r"(a) : "l"(p));
    return a;
}
__device__ __forceinline__ unsigned toOrd(float f) {
    unsigned u = __float_as_uint(f);
    return (u & 0x80000000u) ? ~u : (u | 0x80000000u);
}
__device__ __forceinline__ float fromOrd(unsigned u) {
    unsigned v = (u & 0x80000000u) ? (u & 0x7fffffffu) : ~u;
    return __uint_as_float(v);
}

#define CP_ASYNC16(d, s) asm volatile("cp.async.cg.shared.global [%0], [%1], 16;" :: "r"(d), "l"(s) : "memory")

#define LDSM4(r0, r1, r2, r3, addr) \
    asm volatile("ldmatrix.sync.aligned.m8n8.x4.shared.b16 {%0,%1,%2,%3}, [%4];" \
                 : "=r"(r0), "=r"(r1), "=r"(r2), "=r"(r3) : "r"(addr))

#define MMA16816(c, a, b) \
    asm volatile("mma.sync.aligned.m16n8k16.row.col.f32.bf16.bf16.f32 " \
                 "{%0,%1,%2,%3}, {%4,%5,%6,%7}, {%8,%9}, {%0,%1,%2,%3};" \
                 : "+f"((c)[0]), "+f"((c)[1]), "+f"((c)[2]), "+f"((c)[3]) \
                 : "r"((a)[0]), "r"((a)[1]), "r"((a)[2]), "r"((a)[3]), \
                   "r"((b)[0]), "r"((b)[1]))

// ---------------- kernel 0: fp32 -> bf16 + fused |p|^2 ----------------
__global__ void cvt_kernel(const float* __restrict__ pts, const float* __restrict__ qs) {
    int i = blockIdx.x * blockDim.x + threadIdx.x;   // uint4 index (8 bf16)
    const int half = NPTS * DIM / 8;
    const bool isP = (i < half);
    const float4* src = isP ? (const float4*)pts : (const float4*)qs;
    __nv_bfloat16* dst = isP ? g_pb : g_qb;
    int j = isP ? i : i - half;
    float4 a = src[(size_t)j * 2], b = src[(size_t)j * 2 + 1];
    __nv_bfloat162 p0 = __floats2bfloat162_rn(a.x, a.y);
    __nv_bfloat162 p1 = __floats2bfloat162_rn(a.z, a.w);
    __nv_bfloat162 p2 = __floats2bfloat162_rn(b.x, b.y);
    __nv_bfloat162 p3 = __floats2bfloat162_rn(b.z, b.w);
    uint4 o;
    o.x = *reinterpret_cast<uint32_t*>(&p0);
    o.y = *reinterpret_cast<uint32_t*>(&p1);
    o.z = *reinterpret_cast<uint32_t*>(&p2);
    o.w = *reinterpret_cast<uint32_t*>(&p3);
    reinterpret_cast<uint4*>(dst)[j] = o;
    if (isP) {
        float s = a.x * a.x + a.y * a.y + a.z * a.z + a.w * a.w
                + b.x * b.x + b.y * b.y + b.z * b.z + b.w * b.w;
        #pragma unroll
        for (int off = 8; off; off >>= 1) s += __shfl_xor_sync(0xffffffffu, s, off);
        if ((j & 15) == 0) g_psq[j >> 4] = s;
    }
}

// ---------------- B-tile producer ----------------
__device__ __forceinline__ void issue_tile(uint32_t sb, int t, int b, int tid) {
    const char* srcB = (const char*)(g_pb + (size_t)t * BN * DIM);
    #pragma unroll
    for (int it = 0; it < 8; it++) {
        int idx = it * 256 + tid;
        int r = idx >> 4, c = idx & 15;
        CP_ASYNC16(sb + SM_B + b * 32768 + r * 256 + ((c ^ (r & 7)) << 4),
                   srcB + (size_t)r * 256 + c * 16);
    }
    if (tid < 32)
        CP_ASYNC16(sb + SM_PSQ + b * 512 + tid * 16,
                   (const char*)(g_psq + (size_t)t * BN) + tid * 16);
}

// ---------------- main kernel: HMMA NN search ----------------
__global__ __launch_bounds__(256, 2)
void nn_main(const float* __restrict__ points,
             const float* __restrict__ points_q,
             const float* __restrict__ values,
             float* __restrict__ out) {
    extern __shared__ char smem[];
    const uint32_t sb = smem_u32(smem);
    unsigned* curB = (unsigned*)(smem + SM_CURB);
    unsigned* cntP = (unsigned*)(smem + SM_CNT);
    unsigned* cand = (unsigned*)(smem + SM_CAND);
    unsigned long long* win = (unsigned long long*)(smem + SM_WIN);
    const float* psqS = (const float*)(smem + SM_PSQ);

    const int tid = threadIdx.x, wid = tid >> 5, lane = tid & 31;
    // warp tile 32(M) x 32(N): 2 m-warps x 4 n-warps
    const int warpM = (wid >> 2) * 32, warpN = (wid & 3) * 32;
    const int qBase = blockIdx.x * BQ;

    if (tid < BQ) { curB[tid] = toOrd(3.0e38f); win[tid] = ~0ull; }
    if (tid == 0) *cntP = 0;

    // A tile (64 queries) -> swizzled SMEM
    {
        const char* src = (const char*)(g_qb + (size_t)qBase * DIM);
        #pragma unroll
        for (int it = 0; it < 4; it++) {
            int idx = it * 256 + tid;
            int r = idx >> 4, c = idx & 15;
            CP_ASYNC16(sb + SM_A + r * 256 + ((c ^ (r & 7)) << 4),
                       src + (size_t)r * 256 + c * 16);
        }
    }
    issue_tile(sb, 0, 0, tid);
    asm volatile("cp.async.commit_group;" ::: "memory");
    asm volatile("cp.async.wait_group 0;" ::: "memory");
    __syncthreads();

    // ldmatrix address precompute
    uint32_t aB[2], aX[2];
    #pragma unroll
    for (int m = 0; m < 2; m++) {
        int r = warpM + m * 16 + (lane & 15);
        aB[m] = sb + SM_A + r * 256;
        aX[m] = r & 7;
    }
    const int aHi = lane >> 4;
    uint32_t bOf[2], bX[2];
    #pragma unroll
    for (int p = 0; p < 2; p++) {
        int n = warpN + p * 16 + (lane & 7) + ((lane >> 4) << 3);
        bOf[p] = n * 256;
        bX[p] = n & 7;
    }
    const int bHi = (lane >> 3) & 1;
    const int rLane = lane >> 2;
    const int cLane = (lane & 3) * 2;
    const int quadLead = ((lane & 3) == 0);

    for (int t = 0; t < NTILE; t++) {
        const int b = t & 1;
        if (t + 1 < NTILE) {
            issue_tile(sb, t + 1, b ^ 1, tid);
            asm volatile("cp.async.commit_group;" ::: "memory");
        }

        float acc[2][4][4];
        #pragma unroll
        for (int m = 0; m < 2; m++)
            #pragma unroll
            for (int n = 0; n < 4; n++)
                #pragma unroll
                for (int k = 0; k < 4; k++) acc[m][n][k] = 0.0f;

        const uint32_t bBase = sb + SM_B + b * 32768;
        #pragma unroll
        for (int ks = 0; ks < 8; ks++) {
            uint32_t af[2][4], bf[2][4];
            #pragma unroll
            for (int m = 0; m < 2; m++)
                LDSM4(af[m][0], af[m][1], af[m][2], af[m][3],
                      aB[m] + ((((ks << 1) + aHi) ^ aX[m]) << 4));
            #pragma unroll
            for (int p = 0; p < 2; p++)
                LDSM4(bf[p][0], bf[p][1], bf[p][2], bf[p][3],
                      bBase + bOf[p] + ((((ks << 1) + bHi) ^ bX[p]) << 4));
            #pragma unroll
            for (int m = 0; m < 2; m++)
                #pragma unroll
                for (int n = 0; n < 4; n++)
                    MMA16816(acc[m][n], af[m], &bf[n >> 1][(n & 1) * 2]);
        }

        // ---- pass 1: per-row tile min, quad-reduced, 4 atomics per warp ----
        float ps[4][2];
        #pragma unroll
        for (int n = 0; n < 4; n++) {
            int col = warpN + n * 8 + cLane;
            ps[n][0] = psqS[b * 128 + col];
            ps[n][1] = psqS[b * 128 + col + 1];
        }
        float rowMin[2][2];
        #pragma unroll
        for (int m = 0; m < 2; m++)
            #pragma unroll
            for (int h = 0; h < 2; h++) {
                float mv = 3.0e38f;
                #pragma unroll
                for (int n = 0; n < 4; n++) {
                    mv = fminf(mv, fmaf(acc[m][n][h * 2 + 0], -2.0f, ps[n][0]));
                    mv = fminf(mv, fmaf(acc[m][n][h * 2 + 1], -2.0f, ps[n][1]));
                }
                rowMin[m][h] = mv;
                // quad lanes (same rLane) share this row: fold before atomic
                float qv = mv;
                qv = fminf(qv, __shfl_xor_sync(0xffffffffu, qv, 1));
                qv = fminf(qv, __shfl_xor_sync(0xffffffffu, qv, 2));
                if (quadLead) {
                    int r = warpM + m * 16 + rLane + h * 8;
                    atomicMin(&curB[r], toOrd(qv));
                }
            }

        // ---- single barrier per tile: curB visibility + next B ready ----
        asm volatile("cp.async.wait_group 0;" ::: "memory");
        __syncthreads();

        // ---- pass 2: push margin candidates (gated, rare) ----
        #pragma unroll
        for (int m = 0; m < 2; m++)
            #pragma unroll
            for (int h = 0; h < 2; h++) {
                int r = warpM + m * 16 + rLane + h * 8;
                float lim = fromOrd(curB[r]) + EPS;
                if (rowMin[m][h] < lim) {
                    #pragma unroll
                    for (int n = 0; n < 4; n++)
                        #pragma unroll
                        for (int j = 0; j < 2; j++) {
                            float s = fmaf(acc[m][n][h * 2 + j], -2.0f, ps[n][j]);
                            if (s < lim) {
                                unsigned slot = atomicAdd(cntP, 1u);
                                unsigned nIdx = (unsigned)(t * BN + warpN + n * 8 + cLane + j);
                                if (slot < CAP) cand[slot] = ((unsigned)r << 14) | nIdx;
                            }
                        }
                }
            }
    }
    __syncthreads();

    // ---- exact fp32 rescore: 16-lane groups (masked shuffles!) ----
    unsigned total = *cntP;
    if (total > CAP) total = CAP;
    {
        const int grp = lane >> 4, sl = lane & 15;
        const unsigned gmask = 0xFFFFu << (grp * 16);
        for (unsigned c = (unsigned)(wid * 2 + grp); c < total; c += 16) {
            unsigned pk = cand[c];
            int q = pk >> 14, n = pk & 16383;
            const float4* qp = (const float4*)(points_q + (size_t)(qBase + q) * DIM);
            const float4* pp = (const float4*)(points + (size_t)n * DIM);
            float4 q0 = qp[sl], q1 = qp[sl + 16];
            float4 p0 = pp[sl], p1 = pp[sl + 16];
            float d = q0.x * p0.x + q0.y * p0.y + q0.z * p0.z + q0.w * p0.w
                    + q1.x * p1.x + q1.y * p1.y + q1.z * p1.z + q1.w * p1.w;
            #pragma unroll
            for (int o = 8; o; o >>= 1) d += __shfl_xor_sync(gmask, d, o);
            if (sl == 0) {
                float s = fmaf(d, -2.0f, g_psq[n]);
                unsigned long long key = ((unsigned long long)toOrd(s) << 32) | (unsigned)n;
                atomicMin(&win[q], key);
            }
        }
    }
    __syncthreads();

    // ---- gather values ----
    for (int i = tid; i < BQ * 16; i += 256) {
        int q = i >> 4, c4 = i & 15;
        unsigned idx = (unsigned)(win[q] & 0xFFFFFFFFu);
        *(float4*)(out + (size_t)(qBase + q) * NV + c4 * 4) =
            *(const float4*)(values + (size_t)idx * NV + c4 * 4);
    }
}

// ---------------- launch ----------------
extern "C" void kernel_launch(void* const* d_in, const int* in_sizes, int n_in,
                              void* d_out, int out_size) {
    const float* points   = (const float*)d_in[0];   // [16384,128]
    const float* values   = (const float*)d_in[1];   // [16384,64]
    const float* points_q = (const float*)d_in[2];   // [16384,128]
    float* out = (float*)d_out;

    cvt_kernel<<<(2 * NPTS * DIM / 8) / 256, 256>>>(points, points_q);

    cudaFuncSetAttribute(nn_main, cudaFuncAttributeMaxDynamicSharedMemorySize, SM_TOTAL);
    nn_main<<<NQ / BQ, 256, SM_TOTAL>>>(points, points_q, values, out);
    (void)in_sizes; (void)n_in; (void)out_size;
}

// round 10
// speedup vs baseline: 1.7279x; 1.0705x over previous
#include <cuda_runtime.h>
#include <cuda_bf16.h>
#include <cstdint>

#define NPTS 16384
#define DIM  128
#define NQ   16384
#define NV   64

#define BQ     128
#define BN     128
#define NHALF  8192
#define NTILEH (NHALF / BN)    // 64 tiles per CTA
#define EPS    0.75f
#define CAP    3072

// ---------------- device globals ----------------
__device__ __nv_bfloat16 g_pb[NPTS * DIM];
__device__ __nv_bfloat16 g_qb[NQ * DIM];
__device__ float         g_psq[NPTS];
__device__ unsigned long long g_win[NQ];

// ---------------- SMEM layout (bytes) ----------------
#define SM_A     0        // 128x128 bf16, swizzled    (32768)
#define SM_B     32768    // 2 x 32768                 -> 98304
#define SM_PSQ   98304    // 2 x 512                   -> 99328
#define SM_CURB  99328    // 128 x u32                 -> 99840
#define SM_CNT   99840    //                           -> 99856
#define SM_CAND  99856    // CAP x u32 (12288)         -> 112144
#define SM_TOTAL 112144

// ---------------- helpers ----------------
__device__ __forceinline__ uint32_t smem_u32(const void* p) {
    uint32_t a;
    asm("{ .reg .u64 t; cvta.to.shared.u64 t, %1; cvt.u32.u64 %0, t; }" : "=r"(a) : "l"(p));
    return a;
}
__device__ __forceinline__ unsigned toOrd(float f) {
    unsigned u = __float_as_uint(f);
    return (u & 0x80000000u) ? ~u : (u | 0x80000000u);
}
__device__ __forceinline__ float fromOrd(unsigned u) {
    unsigned v = (u & 0x80000000u) ? (u & 0x7fffffffu) : ~u;
    return __uint_as_float(v);
}

#define CP_ASYNC16(d, s) asm volatile("cp.async.cg.shared.global [%0], [%1], 16;" :: "r"(d), "l"(s) : "memory")

#define LDSM4(r0, r1, r2, r3, addr) \
    asm volatile("ldmatrix.sync.aligned.m8n8.x4.shared.b16 {%0,%1,%2,%3}, [%4];" \
                 : "=r"(r0), "=r"(r1), "=r"(r2), "=r"(r3) : "r"(addr))

#define MMA16816(c, a, b) \
    asm volatile("mma.sync.aligned.m16n8k16.row.col.f32.bf16.bf16.f32 " \
                 "{%0,%1,%2,%3}, {%4,%5,%6,%7}, {%8,%9}, {%0,%1,%2,%3};" \
                 : "+f"((c)[0]), "+f"((c)[1]), "+f"((c)[2]), "+f"((c)[3]) \
                 : "r"((a)[0]), "r"((a)[1]), "r"((a)[2]), "r"((a)[3]), \
                   "r"((b)[0]), "r"((b)[1]))

// ---------------- kernel 0: fp32 -> bf16 + fused |p|^2 + win init ----------------
__global__ void cvt_kernel(const float* __restrict__ pts, const float* __restrict__ qs) {
    int i = blockIdx.x * blockDim.x + threadIdx.x;   // uint4 index (8 bf16)
    if (i < NQ) g_win[i] = ~0ull;
    const int half = NPTS * DIM / 8;
    const bool isP = (i < half);
    const float4* src = isP ? (const float4*)pts : (const float4*)qs;
    __nv_bfloat16* dst = isP ? g_pb : g_qb;
    int j = isP ? i : i - half;
    float4 a = src[(size_t)j * 2], b = src[(size_t)j * 2 + 1];
    __nv_bfloat162 p0 = __floats2bfloat162_rn(a.x, a.y);
    __nv_bfloat162 p1 = __floats2bfloat162_rn(a.z, a.w);
    __nv_bfloat162 p2 = __floats2bfloat162_rn(b.x, b.y);
    __nv_bfloat162 p3 = __floats2bfloat162_rn(b.z, b.w);
    uint4 o;
    o.x = *reinterpret_cast<uint32_t*>(&p0);
    o.y = *reinterpret_cast<uint32_t*>(&p1);
    o.z = *reinterpret_cast<uint32_t*>(&p2);
    o.w = *reinterpret_cast<uint32_t*>(&p3);
    reinterpret_cast<uint4*>(dst)[j] = o;
    if (isP) {
        float s = a.x * a.x + a.y * a.y + a.z * a.z + a.w * a.w
                + b.x * b.x + b.y * b.y + b.z * b.z + b.w * b.w;
        #pragma unroll
        for (int off = 8; off; off >>= 1) s += __shfl_xor_sync(0xffffffffu, s, off);
        if ((j & 15) == 0) g_psq[j >> 4] = s;
    }
}

// ---------------- B-tile producer ----------------
__device__ __forceinline__ void issue_tile(uint32_t sb, int pbase, int t, int b, int tid) {
    const char* srcB = (const char*)(g_pb + (size_t)(pbase + t * BN) * DIM);
    #pragma unroll
    for (int it = 0; it < 8; it++) {
        int idx = it * 256 + tid;
        int r = idx >> 4, c = idx & 15;
        CP_ASYNC16(sb + SM_B + b * 32768 + r * 256 + ((c ^ (r & 7)) << 4),
                   srcB + (size_t)r * 256 + c * 16);
    }
    if (tid < 32)
        CP_ASYNC16(sb + SM_PSQ + b * 512 + tid * 16,
                   (const char*)(g_psq + (size_t)(pbase + t * BN)) + tid * 16);
}

// ---------------- main kernel: HMMA NN search (N-split) ----------------
__global__ __launch_bounds__(256, 2)
void nn_main(const float* __restrict__ points,
             const float* __restrict__ points_q,
             float* __restrict__ out) {
    extern __shared__ char smem[];
    const uint32_t sb = smem_u32(smem);
    unsigned* curB = (unsigned*)(smem + SM_CURB);
    unsigned* cntP = (unsigned*)(smem + SM_CNT);
    unsigned* cand = (unsigned*)(smem + SM_CAND);
    const float* psqS = (const float*)(smem + SM_PSQ);

    const int tid = threadIdx.x, wid = tid >> 5, lane = tid & 31;
    // warp tile 32(M) x 64(N): 4 m-warps x 2 n-warps
    const int warpM = (wid >> 1) * 32, warpN = (wid & 1) * 64;
    const int qBase = (blockIdx.x >> 1) * BQ;
    const int pBase = (blockIdx.x & 1) * NHALF;

    if (tid < BQ) curB[tid] = toOrd(3.0e38f);
    if (tid == 0) *cntP = 0;

    // A tile (128 queries) -> swizzled SMEM
    {
        const char* src = (const char*)(g_qb + (size_t)qBase * DIM);
        #pragma unroll
        for (int it = 0; it < 8; it++) {
            int idx = it * 256 + tid;
            int r = idx >> 4, c = idx & 15;
            CP_ASYNC16(sb + SM_A + r * 256 + ((c ^ (r & 7)) << 4),
                       src + (size_t)r * 256 + c * 16);
        }
    }
    issue_tile(sb, pBase, 0, 0, tid);
    asm volatile("cp.async.commit_group;" ::: "memory");
    asm volatile("cp.async.wait_group 0;" ::: "memory");
    __syncthreads();

    // ldmatrix address precompute
    uint32_t aB[2], aX[2];
    #pragma unroll
    for (int m = 0; m < 2; m++) {
        int r = warpM + m * 16 + (lane & 15);
        aB[m] = sb + SM_A + r * 256;
        aX[m] = r & 7;
    }
    const int aHi = lane >> 4;
    uint32_t bOf[4], bX[4];
    #pragma unroll
    for (int p = 0; p < 4; p++) {
        int n = warpN + p * 16 + (lane & 7) + ((lane >> 4) << 3);
        bOf[p] = n * 256;
        bX[p] = n & 7;
    }
    const int bHi = (lane >> 3) & 1;
    const int rLane = lane >> 2;
    const int cLane = (lane & 3) * 2;
    const int quadLead = ((lane & 3) == 0);

    for (int t = 0; t < NTILEH; t++) {
        const int b = t & 1;
        if (t + 1 < NTILEH) {
            issue_tile(sb, pBase, t + 1, b ^ 1, tid);
            asm volatile("cp.async.commit_group;" ::: "memory");
        }

        float acc[2][8][4];
        #pragma unroll
        for (int m = 0; m < 2; m++)
            #pragma unroll
            for (int n = 0; n < 8; n++)
                #pragma unroll
                for (int k = 0; k < 4; k++) acc[m][n][k] = 0.0f;

        const uint32_t bBase = sb + SM_B + b * 32768;
        #pragma unroll
        for (int ks = 0; ks < 8; ks++) {
            uint32_t af[2][4], bf[4][4];
            #pragma unroll
            for (int m = 0; m < 2; m++)
                LDSM4(af[m][0], af[m][1], af[m][2], af[m][3],
                      aB[m] + ((((ks << 1) + aHi) ^ aX[m]) << 4));
            #pragma unroll
            for (int p = 0; p < 4; p++)
                LDSM4(bf[p][0], bf[p][1], bf[p][2], bf[p][3],
                      bBase + bOf[p] + ((((ks << 1) + bHi) ^ bX[p]) << 4));
            #pragma unroll
            for (int m = 0; m < 2; m++)
                #pragma unroll
                for (int n = 0; n < 8; n++)
                    MMA16816(acc[m][n], af[m], &bf[n >> 1][(n & 1) * 2]);
        }

        // ---- pass 1: per-row tile min, quad-reduced, 4 atomics per warp ----
        float ps[8][2];
        #pragma unroll
        for (int n = 0; n < 8; n++) {
            int col = warpN + n * 8 + cLane;
            ps[n][0] = psqS[b * 128 + col];
            ps[n][1] = psqS[b * 128 + col + 1];
        }
        float rowMin[2][2];
        #pragma unroll
        for (int m = 0; m < 2; m++)
            #pragma unroll
            for (int h = 0; h < 2; h++) {
                float mv = 3.0e38f;
                #pragma unroll
                for (int n = 0; n < 8; n++) {
                    mv = fminf(mv, fmaf(acc[m][n][h * 2 + 0], -2.0f, ps[n][0]));
                    mv = fminf(mv, fmaf(acc[m][n][h * 2 + 1], -2.0f, ps[n][1]));
                }
                rowMin[m][h] = mv;
                float qv = mv;
                qv = fminf(qv, __shfl_xor_sync(0xffffffffu, qv, 1));
                qv = fminf(qv, __shfl_xor_sync(0xffffffffu, qv, 2));
                if (quadLead) {
                    int r = warpM + m * 16 + rLane + h * 8;
                    atomicMin(&curB[r], toOrd(qv));
                }
            }

        // ---- single barrier per tile: curB visibility + next B ready ----
        asm volatile("cp.async.wait_group 0;" ::: "memory");
        __syncthreads();

        // ---- pass 2: push margin candidates (gated, rare) ----
        #pragma unroll
        for (int m = 0; m < 2; m++)
            #pragma unroll
            for (int h = 0; h < 2; h++) {
                int r = warpM + m * 16 + rLane + h * 8;
                float lim = fromOrd(curB[r]) + EPS;
                if (rowMin[m][h] < lim) {
                    #pragma unroll
                    for (int n = 0; n < 8; n++)
                        #pragma unroll
                        for (int j = 0; j < 2; j++) {
                            float s = fmaf(acc[m][n][h * 2 + j], -2.0f, ps[n][j]);
                            if (s < lim) {
                                unsigned slot = atomicAdd(cntP, 1u);
                                unsigned nIdx = (unsigned)(pBase + t * BN + warpN + n * 8 + cLane + j);
                                if (slot < CAP) cand[slot] = ((unsigned)r << 14) | nIdx;
                            }
                        }
                }
            }
    }
    __syncthreads();

    // ---- exact fp32 rescore -> global win (16-lane groups, masked) ----
    unsigned total = *cntP;
    if (total > CAP) total = CAP;
    {
        const int grp = lane >> 4, sl = lane & 15;
        const unsigned gmask = 0xFFFFu << (grp * 16);
        for (unsigned c = (unsigned)(wid * 2 + grp); c < total; c += 16) {
            unsigned pk = cand[c];
            int q = pk >> 14, n = pk & 16383;
            const float4* qp = (const float4*)(points_q + (size_t)(qBase + q) * DIM);
            const float4* pp = (const float4*)(points + (size_t)n * DIM);
            float4 q0 = qp[sl], q1 = qp[sl + 16];
            float4 p0 = pp[sl], p1 = pp[sl + 16];
            float d = q0.x * p0.x + q0.y * p0.y + q0.z * p0.z + q0.w * p0.w
                    + q1.x * p1.x + q1.y * p1.y + q1.z * p1.z + q1.w * p1.w;
            #pragma unroll
            for (int o = 8; o; o >>= 1) d += __shfl_xor_sync(gmask, d, o);
            if (sl == 0) {
                float s = fmaf(d, -2.0f, g_psq[n]);
                unsigned long long key = ((unsigned long long)toOrd(s) << 32) | (unsigned)n;
                atomicMin(&g_win[qBase + q], key);
            }
        }
    }
}

// ---------------- kernel 2: gather ----------------
__global__ void gather_kernel(const float* __restrict__ values, float* __restrict__ out) {
    int i = blockIdx.x * blockDim.x + threadIdx.x;   // float4 index
    int q = i >> 4, c4 = i & 15;
    unsigned idx = (unsigned)(g_win[q] & 0xFFFFFFFFu);
    *(float4*)(out + (size_t)q * NV + c4 * 4) =
        *(const float4*)(values + (size_t)idx * NV + c4 * 4);
}

// ---------------- launch ----------------
extern "C" void kernel_launch(void* const* d_in, const int* in_sizes, int n_in,
                              void* d_out, int out_size) {
    const float* points   = (const float*)d_in[0];   // [16384,128]
    const float* values   = (const float*)d_in[1];   // [16384,64]
    const float* points_q = (const float*)d_in[2];   // [16384,128]
    float* out = (float*)d_out;

    cvt_kernel<<<(2 * NPTS * DIM / 8) / 256, 256>>>(points, points_q);

    cudaFuncSetAttribute(nn_main, cudaFuncAttributeMaxDynamicSharedMemorySize, SM_TOTAL);
    nn_main<<<(NQ / BQ) * 2, 256, SM_TOTAL>>>(points, points_q, out);

    gather_kernel<<<(NQ * 16) / 256, 256>>>(values, out);
    (void)in_sizes; (void)n_in; (void)out_size;
}